// round 15
// baseline (speedup 1.0000x reference)
#include <cuda_runtime.h>
#include <stdint.h>

// Problem constants
#define TSTEPS 23
#define BATCH  128
#define HSZ    512
#define SIsz   11776   // 23*512
#define S2sz   23552   // 2*SI
#define NSPLIT 16
#define KCHUNK 1472    // 23552/16, multiple of 32

// Scratch (static device globals — no allocation allowed)
__device__ float d_H1[TSTEPS*BATCH*HSZ];
__device__ float d_A1[TSTEPS*BATCH*HSZ];
__device__ float d_H2[TSTEPS*BATCH*HSZ];
__device__ float d_A2[TSTEPS*BATCH*HSZ];
__device__ float d_G [BATCH*SIsz];
__device__ float d_F1[BATCH*S2sz];
__device__ float d_P2[NSPLIT*BATCH*HSZ];

// ---------------- tf32x3 GEMM: C[m,n] = sum_k A[m,k]*W[n,k] (+ epilogue) ---
// Split-precision: each fp32 operand v = hi + lo (both tf32); accumulate
// hi*hi + lo*hi + hi*lo into fp32 accumulators -> fp32-accurate GEMM.
// BM=128 BN=64 BK=32, 256 threads, 8 warps (4x2), warp tile 32x32,
// mma.sync.m16n8k8.tf32, cp.async double buffer.
#define BM 128
#define BN 64
#define BK 32
#define ASTRIDE 36              // BK+4: float4-aligned stores, conflict-free frag loads
#define ASZ (BM*ASTRIDE)        // 4608 floats
#define BSZ (BN*ASTRIDE)        // 2304 floats
#define SMEM_BYTES (2*(ASZ+BSZ)*4)   // 55296

__device__ __forceinline__ void cp16(float* s, const float* g) {
    uint32_t sa = (uint32_t)__cvta_generic_to_shared(s);
    asm volatile("cp.async.cg.shared.global [%0], [%1], 16;\n" :: "r"(sa), "l"(g));
}
__device__ __forceinline__ void cp_commit() { asm volatile("cp.async.commit_group;\n"); }
template<int N> __device__ __forceinline__ void cp_wait() {
    asm volatile("cp.async.wait_group %0;\n" :: "n"(N));
}

__device__ __forceinline__ void mma8(float* c, const uint32_t* a, const uint32_t* b) {
    asm volatile("mma.sync.aligned.m16n8k8.row.col.f32.tf32.tf32.f32 "
        "{%0,%1,%2,%3}, {%4,%5,%6,%7}, {%8,%9}, {%0,%1,%2,%3};\n"
        : "+f"(c[0]), "+f"(c[1]), "+f"(c[2]), "+f"(c[3])
        : "r"(a[0]), "r"(a[1]), "r"(a[2]), "r"(a[3]), "r"(b[0]), "r"(b[1]));
}

// Split fp32 into (hi, lo) tf32 pair: v ≈ hi + lo with |lo| <= 2^-11 |v|.
__device__ __forceinline__ void split_tf32(float v, uint32_t& hi, uint32_t& lo) {
    asm("cvt.rna.tf32.f32 %0, %1;\n" : "=r"(hi) : "f"(v));
    float r = v - __uint_as_float(hi);
    asm("cvt.rna.tf32.f32 %0, %1;\n" : "=r"(lo) : "f"(r));
}

// MODE 0: C = v + bias   (row-major, ldc)
// MODE 1: gnn scatter: row=(t*128+b) -> C[b*SI + t*512 + col] = v + bias
// MODE 2: C = relu(v + bias)
// MODE 3: C (+ blockIdx.z*csplit) = v   (split-K partials, no bias)
template<int MODE>
__global__ void __launch_bounds__(256) gemm_tf32(
        const float* __restrict__ A, const float* __restrict__ W,
        const float* __restrict__ bias, float* __restrict__ C,
        int lda, int ldw, int ldc, int k_len, int csplit) {
    extern __shared__ float sm[];
    float* As[2] = { sm, sm + ASZ };
    float* Bs[2] = { sm + 2*ASZ, sm + 2*ASZ + BSZ };

    const int tid = threadIdx.x;
    const int k0  = blockIdx.z * k_len;
    const float* Ag = A + (size_t)blockIdx.y * BM * lda + k0;
    const float* Wg = W + (size_t)blockIdx.x * BN * ldw + k0;

    const int lr = tid >> 3;         // 0..31 : row within tile group
    const int lk = (tid & 7) * 4;    // 0..28 : k offset (float4)
    const int KT = k_len / BK;

    // prologue: stage 0
    {
        const float* ag = Ag + (size_t)lr * lda + lk;
        #pragma unroll
        for (int i = 0; i < 4; i++)
            cp16(&As[0][(lr + 32*i) * ASTRIDE + lk], ag + (size_t)32*i*lda);
        const float* wg = Wg + (size_t)lr * ldw + lk;
        #pragma unroll
        for (int i = 0; i < 2; i++)
            cp16(&Bs[0][(lr + 32*i) * ASTRIDE + lk], wg + (size_t)32*i*ldw);
        cp_commit();
    }

    const int warp = tid >> 5;
    const int lane = tid & 31;
    const int wm = (warp & 3) * 32;
    const int wn = (warp >> 2) * 32;
    const int g4 = lane >> 2;        // 0..7
    const int t4 = lane & 3;         // 0..3

    float acc[2][4][4];
    #pragma unroll
    for (int mi=0;mi<2;mi++)
        #pragma unroll
        for (int ni=0;ni<4;ni++)
            #pragma unroll
            for (int e=0;e<4;e++) acc[mi][ni][e] = 0.f;

    for (int kt = 0; kt < KT; kt++) {
        const int buf = kt & 1;
        if (kt + 1 < KT) {
            const int nb = buf ^ 1;
            const float* ag = Ag + (size_t)lr * lda + (kt+1)*BK + lk;
            #pragma unroll
            for (int i = 0; i < 4; i++)
                cp16(&As[nb][(lr + 32*i) * ASTRIDE + lk], ag + (size_t)32*i*lda);
            const float* wg = Wg + (size_t)lr * ldw + (kt+1)*BK + lk;
            #pragma unroll
            for (int i = 0; i < 2; i++)
                cp16(&Bs[nb][(lr + 32*i) * ASTRIDE + lk], wg + (size_t)32*i*ldw);
            cp_commit();
            cp_wait<1>();
        } else {
            cp_wait<0>();
        }
        __syncthreads();

        const float* Af = As[buf];
        const float* Bf = Bs[buf];
        #pragma unroll
        for (int ks = 0; ks < 4; ks++) {
            const int kk = ks*8 + t4;
            uint32_t ah[2][4], al[2][4], bh[4][2], bl[4][2];
            #pragma unroll
            for (int mi = 0; mi < 2; mi++) {
                const int r = wm + mi*16 + g4;
                split_tf32(Af[r*ASTRIDE + kk],         ah[mi][0], al[mi][0]);
                split_tf32(Af[(r+8)*ASTRIDE + kk],     ah[mi][1], al[mi][1]);
                split_tf32(Af[r*ASTRIDE + kk + 4],     ah[mi][2], al[mi][2]);
                split_tf32(Af[(r+8)*ASTRIDE + kk + 4], ah[mi][3], al[mi][3]);
            }
            #pragma unroll
            for (int ni = 0; ni < 4; ni++) {
                const int c = wn + ni*8 + g4;
                split_tf32(Bf[c*ASTRIDE + kk],     bh[ni][0], bl[ni][0]);
                split_tf32(Bf[c*ASTRIDE + kk + 4], bh[ni][1], bl[ni][1]);
            }
            #pragma unroll
            for (int mi = 0; mi < 2; mi++)
                #pragma unroll
                for (int ni = 0; ni < 4; ni++) {
                    mma8(acc[mi][ni], al[mi], bh[ni]);   // lo*hi
                    mma8(acc[mi][ni], ah[mi], bl[ni]);   // hi*lo
                    mma8(acc[mi][ni], ah[mi], bh[ni]);   // hi*hi
                }
        }
        __syncthreads();
    }

    // epilogue
    float* Co = C + (size_t)blockIdx.z * csplit;
    #pragma unroll
    for (int mi = 0; mi < 2; mi++) {
        #pragma unroll
        for (int ni = 0; ni < 4; ni++) {
            const int row0 = blockIdx.y*BM + wm + mi*16 + g4;
            const int col0 = blockIdx.x*BN + wn + ni*8 + 2*t4;
            #pragma unroll
            for (int e = 0; e < 4; e++) {
                const int row = row0 + ((e >> 1) * 8);
                const int col = col0 + (e & 1);
                const float v = acc[mi][ni][e];
                if (MODE == 0) {
                    Co[(size_t)row*ldc + col] = v + bias[col];
                } else if (MODE == 1) {
                    const int tt = row >> 7, bb = row & 127;
                    Co[(size_t)bb*SIsz + tt*HSZ + col] = v + bias[col];
                } else if (MODE == 2) {
                    const float r2 = v + bias[col];
                    Co[(size_t)row*ldc + col] = r2 > 0.f ? r2 : 0.f;
                } else {
                    Co[(size_t)row*ldc + col] = v;
                }
            }
        }
    }
}

// ------------- time-scan spiking gate: parallel over 65536 (b,h) -----------
// pot += h; fire if pot > tresh: a = pot, pot = 0; else a = 0, pot *= decay.
// (Matches reference exactly: gated = relu(pot - tresh) > 0  <=>  pot > tresh;
//  equality at the boundary does NOT fire, potential decays.)
__global__ void __launch_bounds__(256) scan_gate_kernel(
        const float* __restrict__ H, float* __restrict__ Aout,
        const float* __restrict__ tresh, const float* __restrict__ decay) {
    const int idx = blockIdx.x * blockDim.x + threadIdx.x;   // < 65536
    const int h = idx & (HSZ - 1);
    const float th = tresh[h], dc = decay[h];
    float pot = 0.f;
    #pragma unroll
    for (int t = 0; t < TSTEPS; t++) {
        pot += H[t*(BATCH*HSZ) + idx];
        float a;
        if (pot > th) { a = pot; pot = 0.f; }
        else          { a = 0.f; pot *= dc; }
        Aout[t*(BATCH*HSZ) + idx] = a;
    }
}

// ------------- split-K reduction + bias for the final layer ----------------
__global__ void __launch_bounds__(256) reduce_kernel(
        const float* __restrict__ P, const float* __restrict__ bias,
        float* __restrict__ out) {
    const int idx = blockIdx.x * blockDim.x + threadIdx.x;   // < 65536
    float s = bias[idx & (HSZ - 1)];
    #pragma unroll
    for (int i = 0; i < NSPLIT; i++) s += P[i*(BATCH*HSZ) + idx];
    out[idx] = s;
}

extern "C" void kernel_launch(void* const* d_in, const int* in_sizes, int n_in,
                              void* d_out, int out_size) {
    const float* data   = (const float*)d_in[0];
    const float* fc1_w  = (const float*)d_in[1];
    const float* fc1_b  = (const float*)d_in[2];
    const float* tresh1 = (const float*)d_in[3];
    const float* decay1 = (const float*)d_in[4];
    const float* fc2_w  = (const float*)d_in[5];
    const float* fc2_b  = (const float*)d_in[6];
    const float* tresh2 = (const float*)d_in[7];
    const float* decay2 = (const float*)d_in[8];
    const float* fc3_w  = (const float*)d_in[9];
    const float* fc3_b  = (const float*)d_in[10];
    const float* ffc_w  = (const float*)d_in[11];
    const float* ffc_b  = (const float*)d_in[12];
    const float* ffc2_w = (const float*)d_in[13];
    const float* ffc2_b = (const float*)d_in[14];
    float* out = (float*)d_out;

    float *H1, *A1, *H2, *A2, *G, *F1, *P2;
    cudaGetSymbolAddress((void**)&H1, d_H1);
    cudaGetSymbolAddress((void**)&A1, d_A1);
    cudaGetSymbolAddress((void**)&H2, d_H2);
    cudaGetSymbolAddress((void**)&A2, d_A2);
    cudaGetSymbolAddress((void**)&G,  d_G);
    cudaGetSymbolAddress((void**)&F1, d_F1);
    cudaGetSymbolAddress((void**)&P2, d_P2);

    cudaFuncSetAttribute(gemm_tf32<0>, cudaFuncAttributeMaxDynamicSharedMemorySize, SMEM_BYTES);
    cudaFuncSetAttribute(gemm_tf32<1>, cudaFuncAttributeMaxDynamicSharedMemorySize, SMEM_BYTES);
    cudaFuncSetAttribute(gemm_tf32<2>, cudaFuncAttributeMaxDynamicSharedMemorySize, SMEM_BYTES);
    cudaFuncSetAttribute(gemm_tf32<3>, cudaFuncAttributeMaxDynamicSharedMemorySize, SMEM_BYTES);

    const dim3 blk(256);
    const int MR = TSTEPS*BATCH;   // 2944 rows of (t,b)

    // H1 = data @ fc1^T + b1          [2944, 512] x K=512
    gemm_tf32<0><<<dim3(HSZ/BN, MR/BM, 1), blk, SMEM_BYTES>>>(
        data, fc1_w, fc1_b, H1, 512, 512, 512, 512, 0);
    // A1 = time-scan gate(H1)
    scan_gate_kernel<<<BATCH*HSZ/256, blk>>>(H1, A1, tresh1, decay1);
    // H2 = A1 @ fc2^T + b2
    gemm_tf32<0><<<dim3(HSZ/BN, MR/BM, 1), blk, SMEM_BYTES>>>(
        A1, fc2_w, fc2_b, H2, 512, 512, 512, 512, 0);
    // A2 = time-scan gate(H2)
    scan_gate_kernel<<<BATCH*HSZ/256, blk>>>(H2, A2, tresh2, decay2);
    // G[b, t*512+h] = (A2 @ fc3^T + b3)[t*128+b, h]   (gnn layout scatter)
    gemm_tf32<1><<<dim3(HSZ/BN, MR/BM, 1), blk, SMEM_BYTES>>>(
        A2, fc3_w, fc3_b, G, 512, 512, 0, 512, 0);
    // F1 = relu(G @ ffc^T + fb)       [128, 23552] x K=11776  (dominant: 71 GF -> 213 GF split)
    gemm_tf32<2><<<dim3(S2sz/BN, 1, 1), blk, SMEM_BYTES>>>(
        G, ffc_w, ffc_b, F1, SIsz, SIsz, S2sz, SIsz, 0);
    // P2[s] = F1 @ ffc2^T (K-chunk s) [128, 512] x K=23552, 16-way split-K
    gemm_tf32<3><<<dim3(HSZ/BN, 1, NSPLIT), blk, SMEM_BYTES>>>(
        F1, ffc2_w, nullptr, P2, S2sz, S2sz, HSZ, KCHUNK, BATCH*HSZ);
    // out = sum_s P2[s] + b
    reduce_kernel<<<BATCH*HSZ/256, blk>>>(P2, ffc2_b, out);
}

// round 16
// speedup vs baseline: 1.0000x; 1.0000x over previous
#include <cuda_runtime.h>
#include <stdint.h>

// Problem constants
#define TSTEPS 23
#define BATCH  128
#define HSZ    512
#define SIsz   11776   // 23*512
#define S2sz   23552   // 2*SI
#define NSPLIT 16
#define KCHUNK 1472    // 23552/16, multiple of 32

// Scratch (static device globals — no allocation allowed)
__device__ float d_H1[TSTEPS*BATCH*HSZ];
__device__ float d_A1[TSTEPS*BATCH*HSZ];
__device__ float d_H2[TSTEPS*BATCH*HSZ];
__device__ float d_A2[TSTEPS*BATCH*HSZ];
__device__ float d_G [BATCH*SIsz];
__device__ float d_F1[BATCH*S2sz];
__device__ float d_P2[NSPLIT*BATCH*HSZ];

// ---------------- tf32x3 GEMM: C[m,n] = sum_k A[m,k]*W[n,k] (+ epilogue) ---
// Split-precision: each fp32 operand v = hi + lo (both tf32); accumulate
// hi*hi + lo*hi + hi*lo into fp32 accumulators -> fp32-accurate GEMM.
// BM=128 BN=64 BK=32, 256 threads, 8 warps (4x2), warp tile 32x32,
// mma.sync.m16n8k8.tf32, cp.async double buffer.
#define BM 128
#define BN 64
#define BK 32
#define ASTRIDE 36              // BK+4: float4-aligned stores, conflict-free frag loads
#define ASZ (BM*ASTRIDE)        // 4608 floats
#define BSZ (BN*ASTRIDE)        // 2304 floats
#define SMEM_BYTES (2*(ASZ+BSZ)*4)   // 55296

__device__ __forceinline__ void cp16(float* s, const float* g) {
    uint32_t sa = (uint32_t)__cvta_generic_to_shared(s);
    asm volatile("cp.async.cg.shared.global [%0], [%1], 16;\n" :: "r"(sa), "l"(g));
}
__device__ __forceinline__ void cp_commit() { asm volatile("cp.async.commit_group;\n"); }
template<int N> __device__ __forceinline__ void cp_wait() {
    asm volatile("cp.async.wait_group %0;\n" :: "n"(N));
}

__device__ __forceinline__ void mma8(float* c, const uint32_t* a, const uint32_t* b) {
    asm volatile("mma.sync.aligned.m16n8k8.row.col.f32.tf32.tf32.f32 "
        "{%0,%1,%2,%3}, {%4,%5,%6,%7}, {%8,%9}, {%0,%1,%2,%3};\n"
        : "+f"(c[0]), "+f"(c[1]), "+f"(c[2]), "+f"(c[3])
        : "r"(a[0]), "r"(a[1]), "r"(a[2]), "r"(a[3]), "r"(b[0]), "r"(b[1]));
}

// Split fp32 into (hi, lo) tf32 pair: v ≈ hi + lo with |lo| <= 2^-11 |v|.
__device__ __forceinline__ void split_tf32(float v, uint32_t& hi, uint32_t& lo) {
    asm("cvt.rna.tf32.f32 %0, %1;\n" : "=r"(hi) : "f"(v));
    float r = v - __uint_as_float(hi);
    asm("cvt.rna.tf32.f32 %0, %1;\n" : "=r"(lo) : "f"(r));
}

// MODE 0: C = v + bias   (row-major, ldc)
// MODE 1: gnn scatter: row=(t*128+b) -> C[b*SI + t*512 + col] = v + bias
// MODE 2: C = relu(v + bias)
// MODE 3: C (+ blockIdx.z*csplit) = v   (split-K partials, no bias)
template<int MODE>
__global__ void __launch_bounds__(256) gemm_tf32(
        const float* __restrict__ A, const float* __restrict__ W,
        const float* __restrict__ bias, float* __restrict__ C,
        int lda, int ldw, int ldc, int k_len, int csplit) {
    extern __shared__ float sm[];
    float* As[2] = { sm, sm + ASZ };
    float* Bs[2] = { sm + 2*ASZ, sm + 2*ASZ + BSZ };

    const int tid = threadIdx.x;
    const int k0  = blockIdx.z * k_len;
    const float* Ag = A + (size_t)blockIdx.y * BM * lda + k0;
    const float* Wg = W + (size_t)blockIdx.x * BN * ldw + k0;

    const int lr = tid >> 3;         // 0..31 : row within tile group
    const int lk = (tid & 7) * 4;    // 0..28 : k offset (float4)
    const int KT = k_len / BK;

    // prologue: stage 0
    {
        const float* ag = Ag + (size_t)lr * lda + lk;
        #pragma unroll
        for (int i = 0; i < 4; i++)
            cp16(&As[0][(lr + 32*i) * ASTRIDE + lk], ag + (size_t)32*i*lda);
        const float* wg = Wg + (size_t)lr * ldw + lk;
        #pragma unroll
        for (int i = 0; i < 2; i++)
            cp16(&Bs[0][(lr + 32*i) * ASTRIDE + lk], wg + (size_t)32*i*ldw);
        cp_commit();
    }

    const int warp = tid >> 5;
    const int lane = tid & 31;
    const int wm = (warp & 3) * 32;
    const int wn = (warp >> 2) * 32;
    const int g4 = lane >> 2;        // 0..7
    const int t4 = lane & 3;         // 0..3

    float acc[2][4][4];
    #pragma unroll
    for (int mi=0;mi<2;mi++)
        #pragma unroll
        for (int ni=0;ni<4;ni++)
            #pragma unroll
            for (int e=0;e<4;e++) acc[mi][ni][e] = 0.f;

    for (int kt = 0; kt < KT; kt++) {
        const int buf = kt & 1;
        if (kt + 1 < KT) {
            const int nb = buf ^ 1;
            const float* ag = Ag + (size_t)lr * lda + (kt+1)*BK + lk;
            #pragma unroll
            for (int i = 0; i < 4; i++)
                cp16(&As[nb][(lr + 32*i) * ASTRIDE + lk], ag + (size_t)32*i*lda);
            const float* wg = Wg + (size_t)lr * ldw + (kt+1)*BK + lk;
            #pragma unroll
            for (int i = 0; i < 2; i++)
                cp16(&Bs[nb][(lr + 32*i) * ASTRIDE + lk], wg + (size_t)32*i*ldw);
            cp_commit();
            cp_wait<1>();
        } else {
            cp_wait<0>();
        }
        __syncthreads();

        const float* Af = As[buf];
        const float* Bf = Bs[buf];
        #pragma unroll
        for (int ks = 0; ks < 4; ks++) {
            const int kk = ks*8 + t4;
            uint32_t ah[2][4], al[2][4], bh[4][2], bl[4][2];
            #pragma unroll
            for (int mi = 0; mi < 2; mi++) {
                const int r = wm + mi*16 + g4;
                split_tf32(Af[r*ASTRIDE + kk],         ah[mi][0], al[mi][0]);
                split_tf32(Af[(r+8)*ASTRIDE + kk],     ah[mi][1], al[mi][1]);
                split_tf32(Af[r*ASTRIDE + kk + 4],     ah[mi][2], al[mi][2]);
                split_tf32(Af[(r+8)*ASTRIDE + kk + 4], ah[mi][3], al[mi][3]);
            }
            #pragma unroll
            for (int ni = 0; ni < 4; ni++) {
                const int c = wn + ni*8 + g4;
                split_tf32(Bf[c*ASTRIDE + kk],     bh[ni][0], bl[ni][0]);
                split_tf32(Bf[c*ASTRIDE + kk + 4], bh[ni][1], bl[ni][1]);
            }
            #pragma unroll
            for (int mi = 0; mi < 2; mi++)
                #pragma unroll
                for (int ni = 0; ni < 4; ni++) {
                    mma8(acc[mi][ni], al[mi], bh[ni]);   // lo*hi
                    mma8(acc[mi][ni], ah[mi], bl[ni]);   // hi*lo
                    mma8(acc[mi][ni], ah[mi], bh[ni]);   // hi*hi
                }
        }
        __syncthreads();
    }

    // epilogue
    float* Co = C + (size_t)blockIdx.z * csplit;
    #pragma unroll
    for (int mi = 0; mi < 2; mi++) {
        #pragma unroll
        for (int ni = 0; ni < 4; ni++) {
            const int row0 = blockIdx.y*BM + wm + mi*16 + g4;
            const int col0 = blockIdx.x*BN + wn + ni*8 + 2*t4;
            #pragma unroll
            for (int e = 0; e < 4; e++) {
                const int row = row0 + ((e >> 1) * 8);
                const int col = col0 + (e & 1);
                const float v = acc[mi][ni][e];
                if (MODE == 0) {
                    Co[(size_t)row*ldc + col] = v + bias[col];
                } else if (MODE == 1) {
                    const int tt = row >> 7, bb = row & 127;
                    Co[(size_t)bb*SIsz + tt*HSZ + col] = v + bias[col];
                } else if (MODE == 2) {
                    const float r2 = v + bias[col];
                    Co[(size_t)row*ldc + col] = r2 > 0.f ? r2 : 0.f;
                } else {
                    Co[(size_t)row*ldc + col] = v;
                }
            }
        }
    }
}

// ------------- time-scan spiking gate: parallel over 65536 (b,h) -----------
// pot += h; fire if pot > tresh: a = pot, pot = 0; else a = 0, pot *= decay.
// (Matches reference exactly: gated = relu(pot - tresh) > 0  <=>  pot > tresh;
//  equality at the boundary does NOT fire, potential decays.)
__global__ void __launch_bounds__(256) scan_gate_kernel(
        const float* __restrict__ H, float* __restrict__ Aout,
        const float* __restrict__ tresh, const float* __restrict__ decay) {
    const int idx = blockIdx.x * blockDim.x + threadIdx.x;   // < 65536
    const int h = idx & (HSZ - 1);
    const float th = tresh[h], dc = decay[h];
    float pot = 0.f;
    #pragma unroll
    for (int t = 0; t < TSTEPS; t++) {
        pot += H[t*(BATCH*HSZ) + idx];
        float a;
        if (pot > th) { a = pot; pot = 0.f; }
        else          { a = 0.f; pot *= dc; }
        Aout[t*(BATCH*HSZ) + idx] = a;
    }
}

// ------------- split-K reduction + bias for the final layer ----------------
__global__ void __launch_bounds__(256) reduce_kernel(
        const float* __restrict__ P, const float* __restrict__ bias,
        float* __restrict__ out) {
    const int idx = blockIdx.x * blockDim.x + threadIdx.x;   // < 65536
    float s = bias[idx & (HSZ - 1)];
    #pragma unroll
    for (int i = 0; i < NSPLIT; i++) s += P[i*(BATCH*HSZ) + idx];
    out[idx] = s;
}

extern "C" void kernel_launch(void* const* d_in, const int* in_sizes, int n_in,
                              void* d_out, int out_size) {
    const float* data   = (const float*)d_in[0];
    const float* fc1_w  = (const float*)d_in[1];
    const float* fc1_b  = (const float*)d_in[2];
    const float* tresh1 = (const float*)d_in[3];
    const float* decay1 = (const float*)d_in[4];
    const float* fc2_w  = (const float*)d_in[5];
    const float* fc2_b  = (const float*)d_in[6];
    const float* tresh2 = (const float*)d_in[7];
    const float* decay2 = (const float*)d_in[8];
    const float* fc3_w  = (const float*)d_in[9];
    const float* fc3_b  = (const float*)d_in[10];
    const float* ffc_w  = (const float*)d_in[11];
    const float* ffc_b  = (const float*)d_in[12];
    const float* ffc2_w = (const float*)d_in[13];
    const float* ffc2_b = (const float*)d_in[14];
    float* out = (float*)d_out;

    float *H1, *A1, *H2, *A2, *G, *F1, *P2;
    cudaGetSymbolAddress((void**)&H1, d_H1);
    cudaGetSymbolAddress((void**)&A1, d_A1);
    cudaGetSymbolAddress((void**)&H2, d_H2);
    cudaGetSymbolAddress((void**)&A2, d_A2);
    cudaGetSymbolAddress((void**)&G,  d_G);
    cudaGetSymbolAddress((void**)&F1, d_F1);
    cudaGetSymbolAddress((void**)&P2, d_P2);

    cudaFuncSetAttribute(gemm_tf32<0>, cudaFuncAttributeMaxDynamicSharedMemorySize, SMEM_BYTES);
    cudaFuncSetAttribute(gemm_tf32<1>, cudaFuncAttributeMaxDynamicSharedMemorySize, SMEM_BYTES);
    cudaFuncSetAttribute(gemm_tf32<2>, cudaFuncAttributeMaxDynamicSharedMemorySize, SMEM_BYTES);
    cudaFuncSetAttribute(gemm_tf32<3>, cudaFuncAttributeMaxDynamicSharedMemorySize, SMEM_BYTES);

    const dim3 blk(256);
    const int MR = TSTEPS*BATCH;   // 2944 rows of (t,b)

    // H1 = data @ fc1^T + b1          [2944, 512] x K=512
    gemm_tf32<0><<<dim3(HSZ/BN, MR/BM, 1), blk, SMEM_BYTES>>>(
        data, fc1_w, fc1_b, H1, 512, 512, 512, 512, 0);
    // A1 = time-scan gate(H1)
    scan_gate_kernel<<<BATCH*HSZ/256, blk>>>(H1, A1, tresh1, decay1);
    // H2 = A1 @ fc2^T + b2
    gemm_tf32<0><<<dim3(HSZ/BN, MR/BM, 1), blk, SMEM_BYTES>>>(
        A1, fc2_w, fc2_b, H2, 512, 512, 512, 512, 0);
    // A2 = time-scan gate(H2)
    scan_gate_kernel<<<BATCH*HSZ/256, blk>>>(H2, A2, tresh2, decay2);
    // G[b, t*512+h] = (A2 @ fc3^T + b3)[t*128+b, h]   (gnn layout scatter)
    gemm_tf32<1><<<dim3(HSZ/BN, MR/BM, 1), blk, SMEM_BYTES>>>(
        A2, fc3_w, fc3_b, G, 512, 512, 0, 512, 0);
    // F1 = relu(G @ ffc^T + fb)       [128, 23552] x K=11776  (dominant: 71 GF -> 213 GF split)
    gemm_tf32<2><<<dim3(S2sz/BN, 1, 1), blk, SMEM_BYTES>>>(
        G, ffc_w, ffc_b, F1, SIsz, SIsz, S2sz, SIsz, 0);
    // P2[s] = F1 @ ffc2^T (K-chunk s) [128, 512] x K=23552, 16-way split-K
    gemm_tf32<3><<<dim3(HSZ/BN, 1, NSPLIT), blk, SMEM_BYTES>>>(
        F1, ffc2_w, nullptr, P2, S2sz, S2sz, HSZ, KCHUNK, BATCH*HSZ);
    // out = sum_s P2[s] + b
    reduce_kernel<<<BATCH*HSZ/256, blk>>>(P2, ffc2_b, out);
}

// round 17
// speedup vs baseline: 1.0003x; 1.0003x over previous
#include <cuda_runtime.h>
#include <stdint.h>

// Problem constants
#define TSTEPS 23
#define BATCH  128
#define HSZ    512
#define SIsz   11776   // 23*512
#define S2sz   23552   // 2*SI
#define NSPLIT 16
#define KCHUNK 1472    // 23552/16, multiple of 32

// Scratch (static device globals — no allocation allowed)
__device__ float d_H1[TSTEPS*BATCH*HSZ];
__device__ float d_A1[TSTEPS*BATCH*HSZ];
__device__ float d_H2[TSTEPS*BATCH*HSZ];
__device__ float d_A2[TSTEPS*BATCH*HSZ];
__device__ float d_G [BATCH*SIsz];
__device__ float d_F1[BATCH*S2sz];
__device__ float d_P2[NSPLIT*BATCH*HSZ];

// ---------------- tf32x3 GEMM: C[m,n] = sum_k A[m,k]*W[n,k] (+ epilogue) ---
// Split-precision: each fp32 operand v = hi + lo (both tf32); accumulate
// hi*hi + lo*hi + hi*lo into fp32 accumulators -> fp32-accurate GEMM.
// BM=128 BN=64 BK=32, 256 threads, 8 warps (4x2), warp tile 32x32,
// mma.sync.m16n8k8.tf32, cp.async double buffer.
#define BM 128
#define BN 64
#define BK 32
#define ASTRIDE 36              // BK+4: float4-aligned stores, conflict-free frag loads
#define ASZ (BM*ASTRIDE)        // 4608 floats
#define BSZ (BN*ASTRIDE)        // 2304 floats
#define SMEM_BYTES (2*(ASZ+BSZ)*4)   // 55296

__device__ __forceinline__ void cp16(float* s, const float* g) {
    uint32_t sa = (uint32_t)__cvta_generic_to_shared(s);
    asm volatile("cp.async.cg.shared.global [%0], [%1], 16;\n" :: "r"(sa), "l"(g));
}
__device__ __forceinline__ void cp_commit() { asm volatile("cp.async.commit_group;\n"); }
template<int N> __device__ __forceinline__ void cp_wait() {
    asm volatile("cp.async.wait_group %0;\n" :: "n"(N));
}

__device__ __forceinline__ void mma8(float* c, const uint32_t* a, const uint32_t* b) {
    asm volatile("mma.sync.aligned.m16n8k8.row.col.f32.tf32.tf32.f32 "
        "{%0,%1,%2,%3}, {%4,%5,%6,%7}, {%8,%9}, {%0,%1,%2,%3};\n"
        : "+f"(c[0]), "+f"(c[1]), "+f"(c[2]), "+f"(c[3])
        : "r"(a[0]), "r"(a[1]), "r"(a[2]), "r"(a[3]), "r"(b[0]), "r"(b[1]));
}

// Split fp32 into (hi, lo) tf32 pair: v ≈ hi + lo with |lo| <= 2^-11 |v|.
__device__ __forceinline__ void split_tf32(float v, uint32_t& hi, uint32_t& lo) {
    asm("cvt.rna.tf32.f32 %0, %1;\n" : "=r"(hi) : "f"(v));
    float r = v - __uint_as_float(hi);
    asm("cvt.rna.tf32.f32 %0, %1;\n" : "=r"(lo) : "f"(r));
}

// MODE 0: C = v + bias   (row-major, ldc)
// MODE 1: gnn scatter: row=(t*128+b) -> C[b*SI + t*512 + col] = v + bias
// MODE 2: C = relu(v + bias)
// MODE 3: C (+ blockIdx.z*csplit) = v   (split-K partials, no bias)
template<int MODE>
__global__ void __launch_bounds__(256) gemm_tf32(
        const float* __restrict__ A, const float* __restrict__ W,
        const float* __restrict__ bias, float* __restrict__ C,
        int lda, int ldw, int ldc, int k_len, int csplit) {
    extern __shared__ float sm[];
    float* As[2] = { sm, sm + ASZ };
    float* Bs[2] = { sm + 2*ASZ, sm + 2*ASZ + BSZ };

    const int tid = threadIdx.x;
    const int k0  = blockIdx.z * k_len;
    const float* Ag = A + (size_t)blockIdx.y * BM * lda + k0;
    const float* Wg = W + (size_t)blockIdx.x * BN * ldw + k0;

    const int lr = tid >> 3;         // 0..31 : row within tile group
    const int lk = (tid & 7) * 4;    // 0..28 : k offset (float4)
    const int KT = k_len / BK;

    // prologue: stage 0
    {
        const float* ag = Ag + (size_t)lr * lda + lk;
        #pragma unroll
        for (int i = 0; i < 4; i++)
            cp16(&As[0][(lr + 32*i) * ASTRIDE + lk], ag + (size_t)32*i*lda);
        const float* wg = Wg + (size_t)lr * ldw + lk;
        #pragma unroll
        for (int i = 0; i < 2; i++)
            cp16(&Bs[0][(lr + 32*i) * ASTRIDE + lk], wg + (size_t)32*i*ldw);
        cp_commit();
    }

    const int warp = tid >> 5;
    const int lane = tid & 31;
    const int wm = (warp & 3) * 32;
    const int wn = (warp >> 2) * 32;
    const int g4 = lane >> 2;        // 0..7
    const int t4 = lane & 3;         // 0..3

    float acc[2][4][4];
    #pragma unroll
    for (int mi=0;mi<2;mi++)
        #pragma unroll
        for (int ni=0;ni<4;ni++)
            #pragma unroll
            for (int e=0;e<4;e++) acc[mi][ni][e] = 0.f;

    for (int kt = 0; kt < KT; kt++) {
        const int buf = kt & 1;
        if (kt + 1 < KT) {
            const int nb = buf ^ 1;
            const float* ag = Ag + (size_t)lr * lda + (kt+1)*BK + lk;
            #pragma unroll
            for (int i = 0; i < 4; i++)
                cp16(&As[nb][(lr + 32*i) * ASTRIDE + lk], ag + (size_t)32*i*lda);
            const float* wg = Wg + (size_t)lr * ldw + (kt+1)*BK + lk;
            #pragma unroll
            for (int i = 0; i < 2; i++)
                cp16(&Bs[nb][(lr + 32*i) * ASTRIDE + lk], wg + (size_t)32*i*ldw);
            cp_commit();
            cp_wait<1>();
        } else {
            cp_wait<0>();
        }
        __syncthreads();

        const float* Af = As[buf];
        const float* Bf = Bs[buf];
        #pragma unroll
        for (int ks = 0; ks < 4; ks++) {
            const int kk = ks*8 + t4;
            uint32_t ah[2][4], al[2][4], bh[4][2], bl[4][2];
            #pragma unroll
            for (int mi = 0; mi < 2; mi++) {
                const int r = wm + mi*16 + g4;
                split_tf32(Af[r*ASTRIDE + kk],         ah[mi][0], al[mi][0]);
                split_tf32(Af[(r+8)*ASTRIDE + kk],     ah[mi][1], al[mi][1]);
                split_tf32(Af[r*ASTRIDE + kk + 4],     ah[mi][2], al[mi][2]);
                split_tf32(Af[(r+8)*ASTRIDE + kk + 4], ah[mi][3], al[mi][3]);
            }
            #pragma unroll
            for (int ni = 0; ni < 4; ni++) {
                const int c = wn + ni*8 + g4;
                split_tf32(Bf[c*ASTRIDE + kk],     bh[ni][0], bl[ni][0]);
                split_tf32(Bf[c*ASTRIDE + kk + 4], bh[ni][1], bl[ni][1]);
            }
            #pragma unroll
            for (int mi = 0; mi < 2; mi++)
                #pragma unroll
                for (int ni = 0; ni < 4; ni++) {
                    mma8(acc[mi][ni], al[mi], bh[ni]);   // lo*hi
                    mma8(acc[mi][ni], ah[mi], bl[ni]);   // hi*lo
                    mma8(acc[mi][ni], ah[mi], bh[ni]);   // hi*hi
                }
        }
        __syncthreads();
    }

    // epilogue
    float* Co = C + (size_t)blockIdx.z * csplit;
    #pragma unroll
    for (int mi = 0; mi < 2; mi++) {
        #pragma unroll
        for (int ni = 0; ni < 4; ni++) {
            const int row0 = blockIdx.y*BM + wm + mi*16 + g4;
            const int col0 = blockIdx.x*BN + wn + ni*8 + 2*t4;
            #pragma unroll
            for (int e = 0; e < 4; e++) {
                const int row = row0 + ((e >> 1) * 8);
                const int col = col0 + (e & 1);
                const float v = acc[mi][ni][e];
                if (MODE == 0) {
                    Co[(size_t)row*ldc + col] = v + bias[col];
                } else if (MODE == 1) {
                    const int tt = row >> 7, bb = row & 127;
                    Co[(size_t)bb*SIsz + tt*HSZ + col] = v + bias[col];
                } else if (MODE == 2) {
                    const float r2 = v + bias[col];
                    Co[(size_t)row*ldc + col] = r2 > 0.f ? r2 : 0.f;
                } else {
                    Co[(size_t)row*ldc + col] = v;
                }
            }
        }
    }
}

// ------------- time-scan spiking gate: parallel over 65536 (b,h) -----------
// pot += h; fire if pot > tresh: a = pot, pot = 0; else a = 0, pot *= decay.
// (Matches reference exactly: gated = relu(pot - tresh) > 0  <=>  pot > tresh;
//  equality at the boundary does NOT fire, potential decays.)
__global__ void __launch_bounds__(256) scan_gate_kernel(
        const float* __restrict__ H, float* __restrict__ Aout,
        const float* __restrict__ tresh, const float* __restrict__ decay) {
    const int idx = blockIdx.x * blockDim.x + threadIdx.x;   // < 65536
    const int h = idx & (HSZ - 1);
    const float th = tresh[h], dc = decay[h];
    float pot = 0.f;
    #pragma unroll
    for (int t = 0; t < TSTEPS; t++) {
        pot += H[t*(BATCH*HSZ) + idx];
        float a;
        if (pot > th) { a = pot; pot = 0.f; }
        else          { a = 0.f; pot *= dc; }
        Aout[t*(BATCH*HSZ) + idx] = a;
    }
}

// ------------- split-K reduction + bias for the final layer ----------------
__global__ void __launch_bounds__(256) reduce_kernel(
        const float* __restrict__ P, const float* __restrict__ bias,
        float* __restrict__ out) {
    const int idx = blockIdx.x * blockDim.x + threadIdx.x;   // < 65536
    float s = bias[idx & (HSZ - 1)];
    #pragma unroll
    for (int i = 0; i < NSPLIT; i++) s += P[i*(BATCH*HSZ) + idx];
    out[idx] = s;
}

extern "C" void kernel_launch(void* const* d_in, const int* in_sizes, int n_in,
                              void* d_out, int out_size) {
    const float* data   = (const float*)d_in[0];
    const float* fc1_w  = (const float*)d_in[1];
    const float* fc1_b  = (const float*)d_in[2];
    const float* tresh1 = (const float*)d_in[3];
    const float* decay1 = (const float*)d_in[4];
    const float* fc2_w  = (const float*)d_in[5];
    const float* fc2_b  = (const float*)d_in[6];
    const float* tresh2 = (const float*)d_in[7];
    const float* decay2 = (const float*)d_in[8];
    const float* fc3_w  = (const float*)d_in[9];
    const float* fc3_b  = (const float*)d_in[10];
    const float* ffc_w  = (const float*)d_in[11];
    const float* ffc_b  = (const float*)d_in[12];
    const float* ffc2_w = (const float*)d_in[13];
    const float* ffc2_b = (const float*)d_in[14];
    float* out = (float*)d_out;

    float *H1, *A1, *H2, *A2, *G, *F1, *P2;
    cudaGetSymbolAddress((void**)&H1, d_H1);
    cudaGetSymbolAddress((void**)&A1, d_A1);
    cudaGetSymbolAddress((void**)&H2, d_H2);
    cudaGetSymbolAddress((void**)&A2, d_A2);
    cudaGetSymbolAddress((void**)&G,  d_G);
    cudaGetSymbolAddress((void**)&F1, d_F1);
    cudaGetSymbolAddress((void**)&P2, d_P2);

    cudaFuncSetAttribute(gemm_tf32<0>, cudaFuncAttributeMaxDynamicSharedMemorySize, SMEM_BYTES);
    cudaFuncSetAttribute(gemm_tf32<1>, cudaFuncAttributeMaxDynamicSharedMemorySize, SMEM_BYTES);
    cudaFuncSetAttribute(gemm_tf32<2>, cudaFuncAttributeMaxDynamicSharedMemorySize, SMEM_BYTES);
    cudaFuncSetAttribute(gemm_tf32<3>, cudaFuncAttributeMaxDynamicSharedMemorySize, SMEM_BYTES);

    const dim3 blk(256);
    const int MR = TSTEPS*BATCH;   // 2944 rows of (t,b)

    // H1 = data @ fc1^T + b1          [2944, 512] x K=512
    gemm_tf32<0><<<dim3(HSZ/BN, MR/BM, 1), blk, SMEM_BYTES>>>(
        data, fc1_w, fc1_b, H1, 512, 512, 512, 512, 0);
    // A1 = time-scan gate(H1)
    scan_gate_kernel<<<BATCH*HSZ/256, blk>>>(H1, A1, tresh1, decay1);
    // H2 = A1 @ fc2^T + b2
    gemm_tf32<0><<<dim3(HSZ/BN, MR/BM, 1), blk, SMEM_BYTES>>>(
        A1, fc2_w, fc2_b, H2, 512, 512, 512, 512, 0);
    // A2 = time-scan gate(H2)
    scan_gate_kernel<<<BATCH*HSZ/256, blk>>>(H2, A2, tresh2, decay2);
    // G[b, t*512+h] = (A2 @ fc3^T + b3)[t*128+b, h]   (gnn layout scatter)
    gemm_tf32<1><<<dim3(HSZ/BN, MR/BM, 1), blk, SMEM_BYTES>>>(
        A2, fc3_w, fc3_b, G, 512, 512, 0, 512, 0);
    // F1 = relu(G @ ffc^T + fb)       [128, 23552] x K=11776  (dominant: 71 GF -> 213 GF split)
    gemm_tf32<2><<<dim3(S2sz/BN, 1, 1), blk, SMEM_BYTES>>>(
        G, ffc_w, ffc_b, F1, SIsz, SIsz, S2sz, SIsz, 0);
    // P2[s] = F1 @ ffc2^T (K-chunk s) [128, 512] x K=23552, 16-way split-K
    gemm_tf32<3><<<dim3(HSZ/BN, 1, NSPLIT), blk, SMEM_BYTES>>>(
        F1, ffc2_w, nullptr, P2, S2sz, S2sz, HSZ, KCHUNK, BATCH*HSZ);
    // out = sum_s P2[s] + b
    reduce_kernel<<<BATCH*HSZ/256, blk>>>(P2, ffc2_b, out);
}